// round 1
// baseline (speedup 1.0000x reference)
#include <cuda_runtime.h>
#include <math.h>

#define B_BATCH 64
#define T_ENC   128
#define T_DEC   64
#define D_EMB   512
#define H       1024
#define H3      3072
#define VOCAB   32000

// ---------------- scratch (device globals; no allocation allowed) ----------------
__device__ float g_Gx_enc[T_ENC * B_BATCH * H3];   // per-step input projections (enc), row r = t*B+b
__device__ float g_Gx_dec[T_DEC * B_BATCH * H3];   // word-part projections (dec)
__device__ float g_ctx[B_BATCH * H3];              // ctx projection (constant over t)
__device__ float g_hA[B_BATCH * H];
__device__ float g_hB[B_BATCH * H];
__device__ float g_states[T_DEC * B_BATCH * H];    // decoder hidden states, [t][b][H]
__device__ float g_ghp[2 * B_BATCH * H3];          // K-split partials of h @ Whh^T
__device__ int   g_etok[T_ENC * B_BATCH];
__device__ int   g_dtok[T_DEC * B_BATCH];

// ---------------- token building ----------------
__global__ void build_tokens(const int* __restrict__ x, const int* __restrict__ labels,
                             const int* __restrict__ bosp) {
    int bos = bosp ? bosp[0] : 1;
    int total = T_ENC * B_BATCH + T_DEC * B_BATCH;
    for (int r = blockIdx.x * blockDim.x + threadIdx.x; r < total; r += gridDim.x * blockDim.x) {
        if (r < T_ENC * B_BATCH) {
            int t = r / B_BATCH, b = r % B_BATCH;
            g_etok[r] = x[b * T_ENC + t];
        } else {
            int rr = r - T_ENC * B_BATCH;
            int t = rr / B_BATCH, b = rr % B_BATCH;
            g_dtok[rr] = (t == 0) ? bos : labels[b * T_DEC + (t - 1)];
        }
    }
}

__global__ void zero_kernel(float* __restrict__ p, int n) {
    int i = blockIdx.x * blockDim.x + threadIdx.x;
    if (i < n) p[i] = 0.0f;
}

// ---------------- generic SGEMM: C[m][n] = sum_k Arow(m)[k] * Bm[n][k] + bias[n] ----
// mode 0: Arow(m) = A + m*lda
// mode 1: Arow(m) = A + tokens[m]*lda           (embedding gather)
// mode 2: Arow(m) = A + ((m%Tp)*Bp + m/Tp)*lda  (t,b permute for output GEMM)
// Requires N % 128 == 0, K % 8 == 0. M guarded.
__global__ void __launch_bounds__(256, 2) sgemm_nt(
    const float* __restrict__ A, int lda,
    const float* __restrict__ Bm, int ldb,
    const float* __restrict__ bias,
    float* __restrict__ C, int ldc,
    int M, int K,
    int mode, const int* __restrict__ tokens, int Tp, int Bp)
{
    __shared__ float As[8][128];
    __shared__ float Bs[8][128];
    const int m0 = blockIdx.x * 128;
    const int n0 = blockIdx.y * 128;
    const int tid = threadIdx.x;
    const int tx = tid & 15;
    const int ty = tid >> 4;
    const int lr = tid >> 1;          // tile row 0..127
    const int lk = (tid & 1) * 4;     // k offset 0 or 4

    const float* arow = nullptr;
    {
        int am = m0 + lr;
        if (am < M) {
            long r;
            if (mode == 0) r = am;
            else if (mode == 1) r = tokens[am];
            else r = (long)(am % Tp) * Bp + (am / Tp);
            arow = A + r * (long)lda;
        }
    }
    const float* brow = Bm + (size_t)(n0 + lr) * (size_t)ldb;

    float acc[8][8];
#pragma unroll
    for (int i = 0; i < 8; i++)
#pragma unroll
        for (int j = 0; j < 8; j++) acc[i][j] = 0.0f;

    for (int k0 = 0; k0 < K; k0 += 8) {
        float4 av = arow ? *(const float4*)(arow + k0 + lk) : make_float4(0.f, 0.f, 0.f, 0.f);
        float4 bv = *(const float4*)(brow + k0 + lk);
        __syncthreads();
        As[lk + 0][lr] = av.x; As[lk + 1][lr] = av.y; As[lk + 2][lr] = av.z; As[lk + 3][lr] = av.w;
        Bs[lk + 0][lr] = bv.x; Bs[lk + 1][lr] = bv.y; Bs[lk + 2][lr] = bv.z; Bs[lk + 3][lr] = bv.w;
        __syncthreads();
#pragma unroll
        for (int k = 0; k < 8; k++) {
            float a[8], b[8];
            *(float4*)(a)     = *(const float4*)(&As[k][ty * 4]);
            *(float4*)(a + 4) = *(const float4*)(&As[k][64 + ty * 4]);
            *(float4*)(b)     = *(const float4*)(&Bs[k][tx * 4]);
            *(float4*)(b + 4) = *(const float4*)(&Bs[k][64 + tx * 4]);
#pragma unroll
            for (int i = 0; i < 8; i++)
#pragma unroll
                for (int j = 0; j < 8; j++)
                    acc[i][j] += a[i] * b[j];
        }
    }

#pragma unroll
    for (int i = 0; i < 8; i++) {
        int m = m0 + ((i < 4) ? (ty * 4 + i) : (64 + ty * 4 + (i - 4)));
        if (m >= M) continue;
        float* crow = C + (size_t)m * (size_t)ldc;
        int c0 = n0 + tx * 4;
        int c1 = n0 + 64 + tx * 4;
        float4 v0 = make_float4(acc[i][0], acc[i][1], acc[i][2], acc[i][3]);
        float4 v1 = make_float4(acc[i][4], acc[i][5], acc[i][6], acc[i][7]);
        if (bias) {
            float4 b0 = *(const float4*)(bias + c0);
            float4 b1 = *(const float4*)(bias + c1);
            v0.x += b0.x; v0.y += b0.y; v0.z += b0.z; v0.w += b0.w;
            v1.x += b1.x; v1.y += b1.y; v1.z += b1.z; v1.w += b1.w;
        }
        *(float4*)(crow + c0) = v0;
        *(float4*)(crow + c1) = v1;
    }
}

// ---------------- recurrent step: gh partials = h_prev @ Whh^T (K-split x2) ----------
// grid (64, 2), 128 threads. Block handles 16 j-columns x 3 gates, K/2 each.
__global__ void __launch_bounds__(128) gru_hgemm(
    const float* __restrict__ hprev, int hstride,
    const float* __restrict__ Whh)
{
    __shared__ float hs[16][65];
    __shared__ float ws[16][49];
    const int j0 = blockIdx.x * 16;
    const int ks = blockIdx.y;
    const int kbase = ks * (H / 2);
    const int tid = threadIdx.x;
    const int tx = tid & 15;     // j within tile
    const int ty = tid >> 4;     // 0..7 row group (8 rows each)

    float acc[3][8];
#pragma unroll
    for (int g = 0; g < 3; g++)
#pragma unroll
        for (int r = 0; r < 8; r++) acc[g][r] = 0.0f;

    for (int kt = 0; kt < H / 2; kt += 16) {
        __syncthreads();
#pragma unroll
        for (int i = 0; i < 8; i++) {          // 64 rows x 16 k = 1024 loads
            int idx = tid + i * 128;
            int b = idx >> 4, k = idx & 15;
            hs[k][b] = hprev[b * hstride + kbase + kt + k];
        }
#pragma unroll
        for (int i = 0; i < 6; i++) {          // 48 cols x 16 k = 768 loads
            int idx = tid + i * 128;
            int c = idx >> 4, k = idx & 15;
            int gate = c / 16, jj = c % 16;
            ws[k][c] = Whh[(size_t)(gate * H + j0 + jj) * H + kbase + kt + k];
        }
        __syncthreads();
#pragma unroll
        for (int k = 0; k < 16; k++) {
            float hv[8];
#pragma unroll
            for (int r = 0; r < 8; r++) hv[r] = hs[k][ty * 8 + r];
#pragma unroll
            for (int g = 0; g < 3; g++) {
                float wv = ws[k][g * 16 + tx];
#pragma unroll
                for (int r = 0; r < 8; r++) acc[g][r] += hv[r] * wv;
            }
        }
    }

#pragma unroll
    for (int g = 0; g < 3; g++)
#pragma unroll
        for (int r = 0; r < 8; r++) {
            int b = ty * 8 + r;
            g_ghp[ks * (B_BATCH * H3) + b * H3 + g * H + j0 + tx] = acc[g][r];
        }
}

// ---------------- gate pointwise: consumes gx(+gx2) and gh partials, writes h_new ----
__global__ void gru_gates(const float* __restrict__ gx1,
                          const float* __restrict__ gx2,
                          const float* __restrict__ bhh,
                          const float* __restrict__ hprev, int hstride,
                          float* __restrict__ hout)
{
    int idx = blockIdx.x * blockDim.x + threadIdx.x;   // 64*1024
    int b = idx >> 10;
    int j = idx & 1023;
    const float* gx = gx1 + b * H3;
    float xr = gx[j], xz = gx[j + H], xn = gx[j + 2 * H];
    if (gx2) {
        const float* g2 = gx2 + b * H3;
        xr += g2[j]; xz += g2[j + H]; xn += g2[j + 2 * H];
    }
    const float* p0 = g_ghp + b * H3;
    const float* p1 = g_ghp + B_BATCH * H3 + b * H3;
    float hr = p0[j] + p1[j] + bhh[j];
    float hz = p0[j + H] + p1[j + H] + bhh[j + H];
    float hn = p0[j + 2 * H] + p1[j + 2 * H] + bhh[j + 2 * H];
    float r = 1.0f / (1.0f + expf(-(xr + hr)));
    float z = 1.0f / (1.0f + expf(-(xz + hz)));
    float n = tanhf(xn + r * hn);
    float hp = hprev[b * hstride + j];
    hout[idx] = (1.0f - z) * n + z * hp;
}

// ---------------- host driver ----------------
extern "C" void kernel_launch(void* const* d_in, const int* in_sizes, int n_in,
                              void* d_out, int out_size)
{
    (void)n_in; (void)out_size;
    const int* x      = (const int*)d_in[0];
    const int* labels = (const int*)d_in[1];
    const int* bosp   = nullptr;
    int idx = 2;
    if (in_sizes[2] == 1) { bosp = (const int*)d_in[2]; idx = 3; }
    const float* enc_emb  = (const float*)d_in[idx + 0];
    const float* enc_Wih  = (const float*)d_in[idx + 1];
    const float* enc_Whh  = (const float*)d_in[idx + 2];
    const float* enc_bih  = (const float*)d_in[idx + 3];
    const float* enc_bhh  = (const float*)d_in[idx + 4];
    const float* dec_emb  = (const float*)d_in[idx + 5];
    const float* dec_Wih  = (const float*)d_in[idx + 6];
    const float* dec_Whh  = (const float*)d_in[idx + 7];
    const float* dec_bih  = (const float*)d_in[idx + 8];
    const float* dec_bhh  = (const float*)d_in[idx + 9];
    const float* dec_init = (const float*)d_in[idx + 10];
    const float* lin_W    = (const float*)d_in[idx + 11];
    const float* lin_b    = (const float*)d_in[idx + 12];
    float* out = (float*)d_out;

    float *gxenc, *gxdec, *ctx, *hA, *hB, *states;
    int *etok, *dtok;
    cudaGetSymbolAddress((void**)&gxenc,  g_Gx_enc);
    cudaGetSymbolAddress((void**)&gxdec,  g_Gx_dec);
    cudaGetSymbolAddress((void**)&ctx,    g_ctx);
    cudaGetSymbolAddress((void**)&hA,     g_hA);
    cudaGetSymbolAddress((void**)&hB,     g_hB);
    cudaGetSymbolAddress((void**)&states, g_states);
    cudaGetSymbolAddress((void**)&etok,   g_etok);
    cudaGetSymbolAddress((void**)&dtok,   g_dtok);

    // tokens + h0 = 0
    build_tokens<<<48, 256>>>(x, labels, bosp);
    zero_kernel<<<(B_BATCH * H + 255) / 256, 256>>>(hA, B_BATCH * H);

    // encoder input projections: (8192 x 3072) = gather(enc_emb, etok) @ enc_Wih^T + bih
    sgemm_nt<<<dim3((T_ENC * B_BATCH) / 128, H3 / 128), 256>>>(
        enc_emb, D_EMB, enc_Wih, D_EMB, enc_bih,
        gxenc, H3, T_ENC * B_BATCH, D_EMB, 1, etok, 0, 0);

    // encoder recurrence
    for (int t = 0; t < T_ENC; t++) {
        const float* hp = (t & 1) ? hB : hA;
        float*       ho = (t & 1) ? hA : hB;
        gru_hgemm<<<dim3(64, 2), 128>>>(hp, H, enc_Whh);
        gru_gates<<<(B_BATCH * H) / 256, 256>>>(gxenc + (size_t)t * B_BATCH * H3,
                                                nullptr, enc_bhh, hp, H, ho);
    }
    // T_ENC=128 (even), last write (t=127) went to hA -> final encoder state = hA

    // decoder word projections: (4096 x 3072) = gather(dec_emb, dtok) @ dec_Wih[:, :512]^T + bih
    sgemm_nt<<<dim3((T_DEC * B_BATCH) / 128, H3 / 128), 256>>>(
        dec_emb, D_EMB, dec_Wih, D_EMB + H, dec_bih,
        gxdec, H3, T_DEC * B_BATCH, D_EMB, 1, dtok, 0, 0);

    // ctx projection: (64 x 3072) = e_final @ dec_Wih[:, 512:]^T
    sgemm_nt<<<dim3(1, H3 / 128), 256>>>(
        hA, H, dec_Wih + D_EMB, D_EMB + H, nullptr,
        ctx, H3, B_BATCH, H, 0, nullptr, 0, 0);

    // decoder recurrence (states stored for the output GEMM)
    for (int t = 0; t < T_DEC; t++) {
        const float* hp = (t == 0) ? dec_init : (states + (size_t)(t - 1) * B_BATCH * H);
        int hstride     = (t == 0) ? 0 : H;
        float* ho       = states + (size_t)t * B_BATCH * H;
        gru_hgemm<<<dim3(64, 2), 128>>>(hp, hstride, dec_Whh);
        gru_gates<<<(B_BATCH * H) / 256, 256>>>(gxdec + (size_t)t * B_BATCH * H3,
                                                ctx, dec_bhh, hp, hstride, ho);
    }

    // output GEMM: logits[b*T+t][v] = states[t][b] . lin_W[v] + lin_b[v]
    sgemm_nt<<<dim3((T_DEC * B_BATCH) / 128, VOCAB / 128), 256>>>(
        states, H, lin_W, H, lin_b,
        out, VOCAB, T_DEC * B_BATCH, H, 2, nullptr, T_DEC, B_BATCH);
}

// round 2
// speedup vs baseline: 1.1295x; 1.1295x over previous
#include <cuda_runtime.h>
#include <math.h>

#define B_BATCH 64
#define T_ENC   128
#define T_DEC   64
#define D_EMB   512
#define H       1024
#define H3      3072
#define VOCAB   32000
#define KT      128
#define NBLK    128

// ---------------- scratch (device globals; no allocation allowed) ----------------
__device__ float g_Gx_enc[T_ENC * B_BATCH * H3];   // row r = t*B+b
__device__ float g_Gx_dec[T_DEC * B_BATCH * H3];
__device__ float g_ctx[B_BATCH * H3];
__device__ float g_hA[B_BATCH * H];
__device__ float g_hB[B_BATCH * H];
__device__ float g_h0[H];                          // zeros (encoder h0, stride 0)
__device__ float g_states[T_DEC * B_BATCH * H];    // [t][b][H]
__device__ int   g_etok[T_ENC * B_BATCH];
__device__ int   g_dtok[T_DEC * B_BATCH];

// grid barrier state (sense-reversing; count returns to 0 after each barrier,
// sense flips an even number of times per launch -> deterministic across replays)
__device__ unsigned g_bar_count = 0;
__device__ volatile unsigned g_bar_sense = 0;

__device__ __forceinline__ void grid_barrier(unsigned& sense) {
    __syncthreads();
    if (threadIdx.x == 0) {
        sense ^= 1u;
        __threadfence();
        unsigned arrived = atomicAdd(&g_bar_count, 1u);
        if (arrived == (unsigned)(gridDim.x - 1)) {
            g_bar_count = 0;
            __threadfence();
            g_bar_sense = sense;
        } else {
            while (g_bar_sense != sense) { __nanosleep(32); }
        }
        __threadfence();
    }
    __syncthreads();
}

// ---------------- token building ----------------
__global__ void build_tokens(const int* __restrict__ x, const int* __restrict__ labels,
                             const int* __restrict__ bosp) {
    int bos = bosp ? bosp[0] : 1;
    int total = T_ENC * B_BATCH + T_DEC * B_BATCH;
    for (int r = blockIdx.x * blockDim.x + threadIdx.x; r < total; r += gridDim.x * blockDim.x) {
        if (r < T_ENC * B_BATCH) {
            int t = r / B_BATCH, b = r % B_BATCH;
            g_etok[r] = x[b * T_ENC + t];
        } else {
            int rr = r - T_ENC * B_BATCH;
            int t = rr / B_BATCH, b = rr % B_BATCH;
            g_dtok[rr] = (t == 0) ? bos : labels[b * T_DEC + (t - 1)];
        }
    }
}

__global__ void zero_kernel(float* __restrict__ p, int n) {
    int i = blockIdx.x * blockDim.x + threadIdx.x;
    if (i < n) p[i] = 0.0f;
}

// ---------------- generic SGEMM: C[m][n] = sum_k Arow(m)[k] * Bm[n][k] + bias[n] ----
// mode 0: Arow(m) = A + m*lda
// mode 1: Arow(m) = A + tokens[m]*lda           (embedding gather)
// mode 2: Arow(m) = A + ((m%Tp)*Bp + m/Tp)*lda  (t,b permute for output GEMM)
__global__ void __launch_bounds__(256, 2) sgemm_nt(
    const float* __restrict__ A, int lda,
    const float* __restrict__ Bm, int ldb,
    const float* __restrict__ bias,
    float* __restrict__ C, int ldc,
    int M, int K,
    int mode, const int* __restrict__ tokens, int Tp, int Bp)
{
    __shared__ float As[8][128];
    __shared__ float Bs[8][128];
    const int m0 = blockIdx.x * 128;
    const int n0 = blockIdx.y * 128;
    const int tid = threadIdx.x;
    const int tx = tid & 15;
    const int ty = tid >> 4;
    const int lr = tid >> 1;
    const int lk = (tid & 1) * 4;

    const float* arow = nullptr;
    {
        int am = m0 + lr;
        if (am < M) {
            long r;
            if (mode == 0) r = am;
            else if (mode == 1) r = tokens[am];
            else r = (long)(am % Tp) * Bp + (am / Tp);
            arow = A + r * (long)lda;
        }
    }
    const float* brow = Bm + (size_t)(n0 + lr) * (size_t)ldb;

    float acc[8][8];
#pragma unroll
    for (int i = 0; i < 8; i++)
#pragma unroll
        for (int j = 0; j < 8; j++) acc[i][j] = 0.0f;

    for (int k0 = 0; k0 < K; k0 += 8) {
        float4 av = arow ? *(const float4*)(arow + k0 + lk) : make_float4(0.f, 0.f, 0.f, 0.f);
        float4 bv = *(const float4*)(brow + k0 + lk);
        __syncthreads();
        As[lk + 0][lr] = av.x; As[lk + 1][lr] = av.y; As[lk + 2][lr] = av.z; As[lk + 3][lr] = av.w;
        Bs[lk + 0][lr] = bv.x; Bs[lk + 1][lr] = bv.y; Bs[lk + 2][lr] = bv.z; Bs[lk + 3][lr] = bv.w;
        __syncthreads();
#pragma unroll
        for (int k = 0; k < 8; k++) {
            float a[8], b[8];
            *(float4*)(a)     = *(const float4*)(&As[k][ty * 4]);
            *(float4*)(a + 4) = *(const float4*)(&As[k][64 + ty * 4]);
            *(float4*)(b)     = *(const float4*)(&Bs[k][tx * 4]);
            *(float4*)(b + 4) = *(const float4*)(&Bs[k][64 + tx * 4]);
#pragma unroll
            for (int i = 0; i < 8; i++)
#pragma unroll
                for (int j = 0; j < 8; j++)
                    acc[i][j] += a[i] * b[j];
        }
    }

#pragma unroll
    for (int i = 0; i < 8; i++) {
        int m = m0 + ((i < 4) ? (ty * 4 + i) : (64 + ty * 4 + (i - 4)));
        if (m >= M) continue;
        float* crow = C + (size_t)m * (size_t)ldc;
        int c0 = n0 + tx * 4;
        int c1 = n0 + 64 + tx * 4;
        float4 v0 = make_float4(acc[i][0], acc[i][1], acc[i][2], acc[i][3]);
        float4 v1 = make_float4(acc[i][4], acc[i][5], acc[i][6], acc[i][7]);
        if (bias) {
            float4 b0 = *(const float4*)(bias + c0);
            float4 b1 = *(const float4*)(bias + c1);
            v0.x += b0.x; v0.y += b0.y; v0.z += b0.z; v0.w += b0.w;
            v1.x += b1.x; v1.y += b1.y; v1.z += b1.z; v1.w += b1.w;
        }
        *(float4*)(crow + c0) = v0;
        *(float4*)(crow + c1) = v1;
    }
}

// ---------------- fused persistent GRU recurrence ----------------
// 128 blocks x 256 threads, all resident. Block owns 8 j-columns (all 3 gates,
// all 64 batch rows). One software grid barrier per timestep.
// Thread (jj = tid&7, rg = tid>>3) owns column j0+jj for gates r/z/n and batch
// rows b0 = 2*rg, b1 = 2*rg+1 -> computes h_new directly (no partials, no 2nd kernel).
__global__ void __launch_bounds__(256, 1) gru_persistent(
    const float* __restrict__ gx,    // [T][64][3072]
    const float* __restrict__ gx2,   // [64][3072] or null (decoder ctx)
    const float* __restrict__ Whh,   // [3072][1024]
    const float* __restrict__ bhh,
    const float* __restrict__ h0, int h0stride,
    float* __restrict__ hA, float* __restrict__ hB,   // ping-pong (encoder)
    float* __restrict__ states,      // [T][64][1024] (decoder) or null
    int T)
{
    __shared__ float hs[64][KT + 4];
    __shared__ float ws[24][KT + 4];

    const int tid = threadIdx.x;
    const int jj  = tid & 7;
    const int rg  = tid >> 3;
    const int b0  = rg * 2;
    const int b1  = b0 + 1;
    const int j0  = blockIdx.x * 8;
    const int j   = j0 + jj;

    const float bh0 = bhh[j];
    const float bh1 = bhh[H + j];
    const float bh2 = bhh[2 * H + j];

    unsigned sense = 0;
    if (tid == 0) sense = g_bar_sense;

    for (int t = 0; t < T; t++) {
        const float* hin; int hstride; float* hout;
        if (states) {
            hin = (t == 0) ? h0 : states + (size_t)(t - 1) * B_BATCH * H;
            hstride = (t == 0) ? h0stride : H;
            hout = states + (size_t)t * B_BATCH * H;
        } else {
            hin = (t == 0) ? h0 : (((t - 1) & 1) ? hB : hA);
            hstride = (t == 0) ? h0stride : H;
            hout = (t & 1) ? hB : hA;
        }

        float a00 = 0.f, a01 = 0.f, a10 = 0.f, a11 = 0.f, a20 = 0.f, a21 = 0.f;

        for (int kb = 0; kb < H; kb += KT) {
            __syncthreads();
#pragma unroll
            for (int i = 0; i < 8; i++) {            // hs: 2048 float4
                int idx = tid + i * 256;
                int bb = idx >> 5, kq = idx & 31;
                float4 v = *(const float4*)(hin + (size_t)bb * hstride + kb + kq * 4);
                *(float4*)&hs[bb][kq * 4] = v;
            }
#pragma unroll
            for (int i = 0; i < 3; i++) {            // ws: 768 float4
                int idx = tid + i * 256;
                int c = idx >> 5, kq = idx & 31;
                int g = c >> 3, cj = c & 7;
                float4 v = *(const float4*)(Whh + (size_t)(g * H + j0 + cj) * H + kb + kq * 4);
                *(float4*)&ws[c][kq * 4] = v;
            }
            __syncthreads();
#pragma unroll 8
            for (int k = 0; k < KT; k += 4) {
                float4 hv0 = *(const float4*)&hs[b0][k];
                float4 hv1 = *(const float4*)&hs[b1][k];
                float4 w0  = *(const float4*)&ws[jj][k];
                float4 w1  = *(const float4*)&ws[8 + jj][k];
                float4 w2  = *(const float4*)&ws[16 + jj][k];
                a00 += w0.x * hv0.x; a00 += w0.y * hv0.y; a00 += w0.z * hv0.z; a00 += w0.w * hv0.w;
                a01 += w0.x * hv1.x; a01 += w0.y * hv1.y; a01 += w0.z * hv1.z; a01 += w0.w * hv1.w;
                a10 += w1.x * hv0.x; a10 += w1.y * hv0.y; a10 += w1.z * hv0.z; a10 += w1.w * hv0.w;
                a11 += w1.x * hv1.x; a11 += w1.y * hv1.y; a11 += w1.z * hv1.z; a11 += w1.w * hv1.w;
                a20 += w2.x * hv0.x; a20 += w2.y * hv0.y; a20 += w2.z * hv0.z; a20 += w2.w * hv0.w;
                a21 += w2.x * hv1.x; a21 += w2.y * hv1.y; a21 += w2.z * hv1.z; a21 += w2.w * hv1.w;
            }
        }

        // pointwise gates + state update (thread owns all 3 gates of column j)
        const float* gxt = gx + (size_t)t * B_BATCH * H3;
        float hp0 = hin[(size_t)b0 * hstride + j];
        float hp1 = hin[(size_t)b1 * hstride + j];
        {
            float xr = gxt[(size_t)b0 * H3 + j];
            float xz = gxt[(size_t)b0 * H3 + H + j];
            float xn = gxt[(size_t)b0 * H3 + 2 * H + j];
            if (gx2) {
                xr += gx2[(size_t)b0 * H3 + j];
                xz += gx2[(size_t)b0 * H3 + H + j];
                xn += gx2[(size_t)b0 * H3 + 2 * H + j];
            }
            float r = 1.0f / (1.0f + __expf(-(xr + a00 + bh0)));
            float z = 1.0f / (1.0f + __expf(-(xz + a10 + bh1)));
            float n = tanhf(xn + r * (a20 + bh2));
            hout[(size_t)b0 * H + j] = (1.0f - z) * n + z * hp0;
        }
        {
            float xr = gxt[(size_t)b1 * H3 + j];
            float xz = gxt[(size_t)b1 * H3 + H + j];
            float xn = gxt[(size_t)b1 * H3 + 2 * H + j];
            if (gx2) {
                xr += gx2[(size_t)b1 * H3 + j];
                xz += gx2[(size_t)b1 * H3 + H + j];
                xn += gx2[(size_t)b1 * H3 + 2 * H + j];
            }
            float r = 1.0f / (1.0f + __expf(-(xr + a01 + bh0)));
            float z = 1.0f / (1.0f + __expf(-(xz + a11 + bh1)));
            float n = tanhf(xn + r * (a21 + bh2));
            hout[(size_t)b1 * H + j] = (1.0f - z) * n + z * hp1;
        }
        __threadfence();
        grid_barrier(sense);
    }
}

// ---------------- host driver ----------------
extern "C" void kernel_launch(void* const* d_in, const int* in_sizes, int n_in,
                              void* d_out, int out_size)
{
    (void)n_in; (void)out_size;
    const int* x      = (const int*)d_in[0];
    const int* labels = (const int*)d_in[1];
    const int* bosp   = nullptr;
    int idx = 2;
    if (in_sizes[2] == 1) { bosp = (const int*)d_in[2]; idx = 3; }
    const float* enc_emb  = (const float*)d_in[idx + 0];
    const float* enc_Wih  = (const float*)d_in[idx + 1];
    const float* enc_Whh  = (const float*)d_in[idx + 2];
    const float* enc_bih  = (const float*)d_in[idx + 3];
    const float* enc_bhh  = (const float*)d_in[idx + 4];
    const float* dec_emb  = (const float*)d_in[idx + 5];
    const float* dec_Wih  = (const float*)d_in[idx + 6];
    const float* dec_Whh  = (const float*)d_in[idx + 7];
    const float* dec_bih  = (const float*)d_in[idx + 8];
    const float* dec_bhh  = (const float*)d_in[idx + 9];
    const float* dec_init = (const float*)d_in[idx + 10];
    const float* lin_W    = (const float*)d_in[idx + 11];
    const float* lin_b    = (const float*)d_in[idx + 12];
    float* out = (float*)d_out;

    float *gxenc, *gxdec, *ctx, *hA, *hB, *h0buf, *states;
    int *etok, *dtok;
    cudaGetSymbolAddress((void**)&gxenc,  g_Gx_enc);
    cudaGetSymbolAddress((void**)&gxdec,  g_Gx_dec);
    cudaGetSymbolAddress((void**)&ctx,    g_ctx);
    cudaGetSymbolAddress((void**)&hA,     g_hA);
    cudaGetSymbolAddress((void**)&hB,     g_hB);
    cudaGetSymbolAddress((void**)&h0buf,  g_h0);
    cudaGetSymbolAddress((void**)&states, g_states);
    cudaGetSymbolAddress((void**)&etok,   g_etok);
    cudaGetSymbolAddress((void**)&dtok,   g_dtok);

    build_tokens<<<48, 256>>>(x, labels, bosp);
    zero_kernel<<<4, 256>>>(h0buf, H);

    // encoder input projections: (8192 x 3072) = gather(enc_emb, etok) @ enc_Wih^T + bih
    sgemm_nt<<<dim3((T_ENC * B_BATCH) / 128, H3 / 128), 256>>>(
        enc_emb, D_EMB, enc_Wih, D_EMB, enc_bih,
        gxenc, H3, T_ENC * B_BATCH, D_EMB, 1, etok, 0, 0);

    // encoder recurrence (persistent, 128 barriers). T_ENC=128 -> final state in hB.
    gru_persistent<<<NBLK, 256>>>(gxenc, nullptr, enc_Whh, enc_bhh,
                                  h0buf, 0, hA, hB, nullptr, T_ENC);

    // decoder word projections
    sgemm_nt<<<dim3((T_DEC * B_BATCH) / 128, H3 / 128), 256>>>(
        dec_emb, D_EMB, dec_Wih, D_EMB + H, dec_bih,
        gxdec, H3, T_DEC * B_BATCH, D_EMB, 1, dtok, 0, 0);

    // ctx projection: (64 x 3072) = e_final(hB) @ dec_Wih[:, 512:]^T
    sgemm_nt<<<dim3(1, H3 / 128), 256>>>(
        hB, H, dec_Wih + D_EMB, D_EMB + H, nullptr,
        ctx, H3, B_BATCH, H, 0, nullptr, 0, 0);

    // decoder recurrence (persistent, 64 barriers), writes all states
    gru_persistent<<<NBLK, 256>>>(gxdec, ctx, dec_Whh, dec_bhh,
                                  dec_init, 0, nullptr, nullptr, states, T_DEC);

    // output GEMM: logits[b*T+t][v] = states[t][b] . lin_W[v] + lin_b[v]
    sgemm_nt<<<dim3((T_DEC * B_BATCH) / 128, VOCAB / 128), 256>>>(
        states, H, lin_W, H, lin_b,
        out, VOCAB, T_DEC * B_BATCH, H, 2, nullptr, T_DEC, B_BATCH);
}

// round 4
// speedup vs baseline: 1.1973x; 1.0601x over previous
#include <cuda_runtime.h>
#include <math.h>

#define B_BATCH 64
#define T_ENC   128
#define T_DEC   64
#define D_EMB   512
#define H       1024
#define H3      3072
#define VOCAB   32000
#define KT      128
#define NBLK    128

// ---------------- scratch (device globals; no allocation allowed) ----------------
__device__ float g_Gx_enc[T_ENC * B_BATCH * H3];   // row r = t*B+b
__device__ float g_Gx_dec[T_DEC * B_BATCH * H3];
__device__ float g_ctx[B_BATCH * H3];
__device__ float g_hA[B_BATCH * H];
__device__ float g_hB[B_BATCH * H];
__device__ float g_h0[H];                          // zeros (encoder h0, stride 0)
__device__ float g_states[T_DEC * B_BATCH * H];    // [t][b][H]
__device__ int   g_etok[T_ENC * B_BATCH];
__device__ int   g_dtok[T_DEC * B_BATCH];

// grid barrier state (sense-reversing)
__device__ unsigned g_bar_count = 0;
__device__ volatile unsigned g_bar_sense = 0;

__device__ __forceinline__ void grid_barrier(unsigned& sense) {
    __syncthreads();
    if (threadIdx.x == 0) {
        sense ^= 1u;
        __threadfence();
        unsigned arrived = atomicAdd(&g_bar_count, 1u);
        if (arrived == (unsigned)(gridDim.x - 1)) {
            g_bar_count = 0;
            __threadfence();
            g_bar_sense = sense;
        } else {
            while (g_bar_sense != sense) { __nanosleep(32); }
        }
        __threadfence();
    }
    __syncthreads();
}

// ---------------- token building ----------------
__global__ void build_tokens(const int* __restrict__ x, const int* __restrict__ labels,
                             const int* __restrict__ bosp) {
    int bos = bosp ? bosp[0] : 1;
    int total = T_ENC * B_BATCH + T_DEC * B_BATCH;
    for (int r = blockIdx.x * blockDim.x + threadIdx.x; r < total; r += gridDim.x * blockDim.x) {
        if (r < T_ENC * B_BATCH) {
            int t = r / B_BATCH, b = r % B_BATCH;
            g_etok[r] = x[b * T_ENC + t];
        } else {
            int rr = r - T_ENC * B_BATCH;
            int t = rr / B_BATCH, b = rr % B_BATCH;
            g_dtok[rr] = (t == 0) ? bos : labels[b * T_DEC + (t - 1)];
        }
    }
}

__global__ void zero_kernel(float* __restrict__ p, int n) {
    int i = blockIdx.x * blockDim.x + threadIdx.x;
    if (i < n) p[i] = 0.0f;
}

__device__ __forceinline__ unsigned f2tf32(float v) {
    unsigned u;
    asm("cvt.rna.tf32.f32 %0, %1;" : "=r"(u) : "f"(v));
    return u;
}

// ---------------- tf32 tensor-core GEMM: C[m][n] = Arow(m).Bm[n] + bias[n] ----------
// mode 0: Arow(m)=A+m*lda   mode 1: Arow(m)=A+tokens[m]*lda
// mode 2: Arow(m)=A+((m%Tp)*Bp+m/Tp)*lda
// Tiles: 128(M) x 128(N) x 32(K). 8 warps, each 32x64. Requires N%128==0, K%32==0.
__global__ void __launch_bounds__(256, 2) tf32_gemm(
    const float* __restrict__ A, int lda,
    const float* __restrict__ Bm, int ldb,
    const float* __restrict__ bias,
    float* __restrict__ C, int ldc,
    int M, int K,
    int mode, const int* __restrict__ tokens, int Tp, int Bp)
{
    __shared__ float As[128][36];
    __shared__ float Bs[128][36];

    const int m0 = blockIdx.x * 128;
    const int n0 = blockIdx.y * 128;
    const int tid  = threadIdx.x;
    const int wid  = tid >> 5;
    const int lane = tid & 31;
    const int warp_m = wid >> 1;          // 0..3  -> 32 rows
    const int warp_n = wid & 1;           // 0..1  -> 64 cols
    const int grp  = lane >> 2;           // 0..7
    const int qid  = lane & 3;            // 0..3

    // per-thread load row (fixed): row = tid>>1, k-half = (tid&1)*16
    const int lrow = tid >> 1;
    const int lkh  = (tid & 1) * 16;

    const float* arow = nullptr;
    {
        int am = m0 + lrow;
        if (am < M) {
            long r;
            if (mode == 0) r = am;
            else if (mode == 1) r = tokens[am];
            else r = (long)(am % Tp) * Bp + (am / Tp);
            arow = A + r * (long)lda;
        }
    }
    const float* brow = Bm + (size_t)(n0 + lrow) * (size_t)ldb;

    float acc[2][8][4];
#pragma unroll
    for (int i = 0; i < 2; i++)
#pragma unroll
        for (int j = 0; j < 8; j++)
#pragma unroll
            for (int c = 0; c < 4; c++) acc[i][j][c] = 0.0f;

    for (int k0 = 0; k0 < K; k0 += 32) {
        __syncthreads();
#pragma unroll
        for (int i = 0; i < 4; i++) {
            float4 av = arow ? *(const float4*)(arow + k0 + lkh + i * 4)
                             : make_float4(0.f, 0.f, 0.f, 0.f);
            As[lrow][lkh + i * 4 + 0] = __uint_as_float(f2tf32(av.x));
            As[lrow][lkh + i * 4 + 1] = __uint_as_float(f2tf32(av.y));
            As[lrow][lkh + i * 4 + 2] = __uint_as_float(f2tf32(av.z));
            As[lrow][lkh + i * 4 + 3] = __uint_as_float(f2tf32(av.w));
            float4 bv = *(const float4*)(brow + k0 + lkh + i * 4);
            Bs[lrow][lkh + i * 4 + 0] = __uint_as_float(f2tf32(bv.x));
            Bs[lrow][lkh + i * 4 + 1] = __uint_as_float(f2tf32(bv.y));
            Bs[lrow][lkh + i * 4 + 2] = __uint_as_float(f2tf32(bv.z));
            Bs[lrow][lkh + i * 4 + 3] = __uint_as_float(f2tf32(bv.w));
        }
        __syncthreads();

#pragma unroll
        for (int ks = 0; ks < 32; ks += 8) {
            // A fragments: 2 m-tiles of 16
            unsigned af[2][4];
#pragma unroll
            for (int mt = 0; mt < 2; mt++) {
                int r0 = warp_m * 32 + mt * 16 + grp;
                af[mt][0] = __float_as_uint(As[r0][ks + qid]);
                af[mt][1] = __float_as_uint(As[r0 + 8][ks + qid]);
                af[mt][2] = __float_as_uint(As[r0][ks + qid + 4]);
                af[mt][3] = __float_as_uint(As[r0 + 8][ks + qid + 4]);
            }
            // B fragments: 8 n-tiles of 8
            unsigned bf[8][2];
#pragma unroll
            for (int nt = 0; nt < 8; nt++) {
                int nr = warp_n * 64 + nt * 8 + grp;
                bf[nt][0] = __float_as_uint(Bs[nr][ks + qid]);
                bf[nt][1] = __float_as_uint(Bs[nr][ks + qid + 4]);
            }
#pragma unroll
            for (int mt = 0; mt < 2; mt++)
#pragma unroll
                for (int nt = 0; nt < 8; nt++) {
                    asm volatile(
                        "mma.sync.aligned.m16n8k8.row.col.f32.tf32.tf32.f32 "
                        "{%0,%1,%2,%3}, {%4,%5,%6,%7}, {%8,%9}, {%0,%1,%2,%3};\n"
                        : "+f"(acc[mt][nt][0]), "+f"(acc[mt][nt][1]),
                          "+f"(acc[mt][nt][2]), "+f"(acc[mt][nt][3])
                        : "r"(af[mt][0]), "r"(af[mt][1]), "r"(af[mt][2]), "r"(af[mt][3]),
                          "r"(bf[nt][0]), "r"(bf[nt][1]));
                }
        }
    }

    // epilogue
#pragma unroll
    for (int mt = 0; mt < 2; mt++) {
#pragma unroll
        for (int half = 0; half < 2; half++) {
            int m = m0 + warp_m * 32 + mt * 16 + grp + half * 8;
            if (m >= M) continue;
            float* crow = C + (size_t)m * (size_t)ldc;
#pragma unroll
            for (int nt = 0; nt < 8; nt++) {
                int col = n0 + warp_n * 64 + nt * 8 + 2 * qid;
                float v0 = acc[mt][nt][half * 2 + 0];
                float v1 = acc[mt][nt][half * 2 + 1];
                if (bias) { v0 += bias[col]; v1 += bias[col + 1]; }
                *(float2*)(crow + col) = make_float2(v0, v1);
            }
        }
    }
}

// ---------------- fused persistent GRU recurrence (unchanged from R2) ----------------
__global__ void __launch_bounds__(256, 1) gru_persistent(
    const float* __restrict__ gx,    // [T][64][3072]
    const float* __restrict__ gx2,   // [64][3072] or null
    const float* __restrict__ Whh,   // [3072][1024]
    const float* __restrict__ bhh,
    const float* __restrict__ h0, int h0stride,
    float* __restrict__ hA, float* __restrict__ hB,
    float* __restrict__ states,
    int T)
{
    __shared__ float hs[64][KT + 4];
    __shared__ float ws[24][KT + 4];

    const int tid = threadIdx.x;
    const int jj  = tid & 7;
    const int rg  = tid >> 3;
    const int b0  = rg * 2;
    const int b1  = b0 + 1;
    const int j0  = blockIdx.x * 8;
    const int j   = j0 + jj;

    const float bh0 = bhh[j];
    const float bh1 = bhh[H + j];
    const float bh2 = bhh[2 * H + j];

    unsigned sense = 0;
    if (tid == 0) sense = g_bar_sense;

    for (int t = 0; t < T; t++) {
        const float* hin; int hstride; float* hout;
        if (states) {
            hin = (t == 0) ? h0 : states + (size_t)(t - 1) * B_BATCH * H;
            hstride = (t == 0) ? h0stride : H;
            hout = states + (size_t)t * B_BATCH * H;
        } else {
            hin = (t == 0) ? h0 : (((t - 1) & 1) ? hB : hA);
            hstride = (t == 0) ? h0stride : H;
            hout = (t & 1) ? hB : hA;
        }

        float a00 = 0.f, a01 = 0.f, a10 = 0.f, a11 = 0.f, a20 = 0.f, a21 = 0.f;

        for (int kb = 0; kb < H; kb += KT) {
            __syncthreads();
#pragma unroll
            for (int i = 0; i < 8; i++) {
                int idx = tid + i * 256;
                int bb = idx >> 5, kq = idx & 31;
                float4 v = *(const float4*)(hin + (size_t)bb * hstride + kb + kq * 4);
                *(float4*)&hs[bb][kq * 4] = v;
            }
#pragma unroll
            for (int i = 0; i < 3; i++) {
                int idx = tid + i * 256;
                int c = idx >> 5, kq = idx & 31;
                int g = c >> 3, cj = c & 7;
                float4 v = *(const float4*)(Whh + (size_t)(g * H + j0 + cj) * H + kb + kq * 4);
                *(float4*)&ws[c][kq * 4] = v;
            }
            __syncthreads();
#pragma unroll 8
            for (int k = 0; k < KT; k += 4) {
                float4 hv0 = *(const float4*)&hs[b0][k];
                float4 hv1 = *(const float4*)&hs[b1][k];
                float4 w0  = *(const float4*)&ws[jj][k];
                float4 w1  = *(const float4*)&ws[8 + jj][k];
                float4 w2  = *(const float4*)&ws[16 + jj][k];
                a00 += w0.x * hv0.x; a00 += w0.y * hv0.y; a00 += w0.z * hv0.z; a00 += w0.w * hv0.w;
                a01 += w0.x * hv1.x; a01 += w0.y * hv1.y; a01 += w0.z * hv1.z; a01 += w0.w * hv1.w;
                a10 += w1.x * hv0.x; a10 += w1.y * hv0.y; a10 += w1.z * hv0.z; a10 += w1.w * hv0.w;
                a11 += w1.x * hv1.x; a11 += w1.y * hv1.y; a11 += w1.z * hv1.z; a11 += w1.w * hv1.w;
                a20 += w2.x * hv0.x; a20 += w2.y * hv0.y; a20 += w2.z * hv0.z; a20 += w2.w * hv0.w;
                a21 += w2.x * hv1.x; a21 += w2.y * hv1.y; a21 += w2.z * hv1.z; a21 += w2.w * hv1.w;
            }
        }

        const float* gxt = gx + (size_t)t * B_BATCH * H3;
        float hp0 = hin[(size_t)b0 * hstride + j];
        float hp1 = hin[(size_t)b1 * hstride + j];
        {
            float xr = gxt[(size_t)b0 * H3 + j];
            float xz = gxt[(size_t)b0 * H3 + H + j];
            float xn = gxt[(size_t)b0 * H3 + 2 * H + j];
            if (gx2) {
                xr += gx2[(size_t)b0 * H3 + j];
                xz += gx2[(size_t)b0 * H3 + H + j];
                xn += gx2[(size_t)b0 * H3 + 2 * H + j];
            }
            float r = 1.0f / (1.0f + __expf(-(xr + a00 + bh0)));
            float z = 1.0f / (1.0f + __expf(-(xz + a10 + bh1)));
            float n = tanhf(xn + r * (a20 + bh2));
            hout[(size_t)b0 * H + j] = (1.0f - z) * n + z * hp0;
        }
        {
            float xr = gxt[(size_t)b1 * H3 + j];
            float xz = gxt[(size_t)b1 * H3 + H + j];
            float xn = gxt[(size_t)b1 * H3 + 2 * H + j];
            if (gx2) {
                xr += gx2[(size_t)b1 * H3 + j];
                xz += gx2[(size_t)b1 * H3 + H + j];
                xn += gx2[(size_t)b1 * H3 + 2 * H + j];
            }
            float r = 1.0f / (1.0f + __expf(-(xr + a01 + bh0)));
            float z = 1.0f / (1.0f + __expf(-(xz + a11 + bh1)));
            float n = tanhf(xn + r * (a21 + bh2));
            hout[(size_t)b1 * H + j] = (1.0f - z) * n + z * hp1;
        }
        __threadfence();
        grid_barrier(sense);
    }
}

// ---------------- host driver ----------------
extern "C" void kernel_launch(void* const* d_in, const int* in_sizes, int n_in,
                              void* d_out, int out_size)
{
    (void)n_in; (void)out_size;
    const int* x      = (const int*)d_in[0];
    const int* labels = (const int*)d_in[1];
    const int* bosp   = nullptr;
    int idx = 2;
    if (in_sizes[2] == 1) { bosp = (const int*)d_in[2]; idx = 3; }
    const float* enc_emb  = (const float*)d_in[idx + 0];
    const float* enc_Wih  = (const float*)d_in[idx + 1];
    const float* enc_Whh  = (const float*)d_in[idx + 2];
    const float* enc_bih  = (const float*)d_in[idx + 3];
    const float* enc_bhh  = (const float*)d_in[idx + 4];
    const float* dec_emb  = (const float*)d_in[idx + 5];
    const float* dec_Wih  = (const float*)d_in[idx + 6];
    const float* dec_Whh  = (const float*)d_in[idx + 7];
    const float* dec_bih  = (const float*)d_in[idx + 8];
    const float* dec_bhh  = (const float*)d_in[idx + 9];
    const float* dec_init = (const float*)d_in[idx + 10];
    const float* lin_W    = (const float*)d_in[idx + 11];
    const float* lin_b    = (const float*)d_in[idx + 12];
    float* out = (float*)d_out;

    float *gxenc, *gxdec, *ctx, *hA, *hB, *h0buf, *states;
    int *etok, *dtok;
    cudaGetSymbolAddress((void**)&gxenc,  g_Gx_enc);
    cudaGetSymbolAddress((void**)&gxdec,  g_Gx_dec);
    cudaGetSymbolAddress((void**)&ctx,    g_ctx);
    cudaGetSymbolAddress((void**)&hA,     g_hA);
    cudaGetSymbolAddress((void**)&hB,     g_hB);
    cudaGetSymbolAddress((void**)&h0buf,  g_h0);
    cudaGetSymbolAddress((void**)&states, g_states);
    cudaGetSymbolAddress((void**)&etok,   g_etok);
    cudaGetSymbolAddress((void**)&dtok,   g_dtok);

    build_tokens<<<48, 256>>>(x, labels, bosp);
    zero_kernel<<<4, 256>>>(h0buf, H);

    // encoder input projections: (8192 x 3072 x 512)
    tf32_gemm<<<dim3((T_ENC * B_BATCH) / 128, H3 / 128), 256>>>(
        enc_emb, D_EMB, enc_Wih, D_EMB, enc_bih,
        gxenc, H3, T_ENC * B_BATCH, D_EMB, 1, etok, 0, 0);

    // encoder recurrence (persistent). T_ENC=128 -> final state in hB.
    gru_persistent<<<NBLK, 256>>>(gxenc, nullptr, enc_Whh, enc_bhh,
                                  h0buf, 0, hA, hB, nullptr, T_ENC);

    // decoder word projections: (4096 x 3072 x 512)
    tf32_gemm<<<dim3((T_DEC * B_BATCH) / 128, H3 / 128), 256>>>(
        dec_emb, D_EMB, dec_Wih, D_EMB + H, dec_bih,
        gxdec, H3, T_DEC * B_BATCH, D_EMB, 1, dtok, 0, 0);

    // ctx projection: (64 x 3072 x 1024)
    tf32_gemm<<<dim3(1, H3 / 128), 256>>>(
        hB, H, dec_Wih + D_EMB, D_EMB + H, nullptr,
        ctx, H3, B_BATCH, H, 0, nullptr, 0, 0);

    // decoder recurrence (persistent), writes all states
    gru_persistent<<<NBLK, 256>>>(gxdec, ctx, dec_Whh, dec_bhh,
                                  dec_init, 0, nullptr, nullptr, states, T_DEC);

    // output GEMM: (4096 x 32000 x 1024), logits[b*T+t][v]
    tf32_gemm<<<dim3((T_DEC * B_BATCH) / 128, VOCAB / 128), 256>>>(
        states, H, lin_W, H, lin_b,
        out, VOCAB, T_DEC * B_BATCH, H, 2, nullptr, T_DEC, B_BATCH);
}

// round 7
// speedup vs baseline: 2.2890x; 1.9117x over previous
#include <cuda_runtime.h>
#include <cuda_fp16.h>
#include <math.h>
#include <stdint.h>

#define B_BATCH 64
#define T_ENC   128
#define T_DEC   64
#define D_EMB   512
#define H       1024
#define H3      3072
#define VOCAB   32000
#define KT      128
#define NBLK    128
#define M_ROWS  (T_DEC * B_BATCH)      // 4096

// ---------------- scratch (device globals; no allocation allowed) ----------------
__device__ float g_Gx_enc[T_ENC * B_BATCH * H3];
__device__ float g_Gx_dec[T_DEC * B_BATCH * H3];
__device__ float g_ctx[B_BATCH * H3];
__device__ float g_hA[B_BATCH * H];
__device__ float g_hB[B_BATCH * H];
__device__ float g_h0[H];
__device__ float g_states[T_DEC * B_BATCH * H];    // [t][b][H]
__device__ int   g_etok[T_ENC * B_BATCH];
__device__ int   g_dtok[T_DEC * B_BATCH];
// fp16 operand copies
__device__ __half g_embE[VOCAB * D_EMB];
__device__ __half g_embD[VOCAB * D_EMB];
__device__ __half g_wihE[H3 * D_EMB];
__device__ __half g_wihD[H3 * (D_EMB + H)];
__device__ __half g_linW[VOCAB * H];
__device__ __half g_statesH[M_ROWS * H];           // still [t][b][H] order
__device__ __half g_hBH[B_BATCH * H];

// grid barrier state
__device__ unsigned g_bar_count = 0;
__device__ volatile unsigned g_bar_sense = 0;

__device__ __forceinline__ void grid_barrier(unsigned& sense) {
    __syncthreads();
    if (threadIdx.x == 0) {
        sense ^= 1u;
        __threadfence();
        unsigned arrived = atomicAdd(&g_bar_count, 1u);
        if (arrived == (unsigned)(gridDim.x - 1)) {
            g_bar_count = 0;
            __threadfence();
            g_bar_sense = sense;
        } else {
            while (g_bar_sense != sense) { __nanosleep(32); }
        }
        __threadfence();
    }
    __syncthreads();
}

__device__ __forceinline__ uint32_t smem_u32(const void* p) {
    uint32_t a;
    asm("{ .reg .u64 t; cvta.to.shared.u64 t, %1; cvt.u32.u64 %0, t; }" : "=r"(a) : "l"(p));
    return a;
}

// ---------------- token building ----------------
__global__ void build_tokens(const int* __restrict__ x, const int* __restrict__ labels,
                             const int* __restrict__ bosp) {
    int bos = bosp ? bosp[0] : 1;
    int total = T_ENC * B_BATCH + T_DEC * B_BATCH;
    for (int r = blockIdx.x * blockDim.x + threadIdx.x; r < total; r += gridDim.x * blockDim.x) {
        if (r < T_ENC * B_BATCH) {
            int t = r / B_BATCH, b = r % B_BATCH;
            g_etok[r] = x[b * T_ENC + t];
        } else {
            int rr = r - T_ENC * B_BATCH;
            int t = rr / B_BATCH, b = rr % B_BATCH;
            g_dtok[rr] = (t == 0) ? bos : labels[b * T_DEC + (t - 1)];
        }
    }
}

__global__ void zero_kernel(float* __restrict__ p, int n) {
    int i = blockIdx.x * blockDim.x + threadIdx.x;
    if (i < n) p[i] = 0.0f;
}

// ---------------- fp32 -> fp16 conversion ----------------
__global__ void conv_h(const float* __restrict__ src, __half* __restrict__ dst, int n4) {
    int i = blockIdx.x * blockDim.x + threadIdx.x;
    if (i >= n4) return;
    float4 v = *(const float4*)(src + i * 4);
    *(__half2*)(dst + i * 4)     = __floats2half2_rn(v.x, v.y);
    *(__half2*)(dst + i * 4 + 2) = __floats2half2_rn(v.z, v.w);
}

// ---------------- fp16 HMMA GEMM: C[m][n] = Arow(m).Bm[n] + bias[n] ----------------
// mode 0: Arow(m)=A+m*lda   mode 1: Arow(m)=A+tokens[m]*lda
// mode 2: Arow(m)=A+((m%Tp)*Bp+m/Tp)*lda
// Tile 128(M) x 128(N) x 32(K). 8 warps, each 32x64. N%128==0, K%32==0, M guarded.
__global__ void __launch_bounds__(256, 2) h16_gemm(
    const __half* __restrict__ A, int lda,
    const __half* __restrict__ Bm, int ldb,
    const float* __restrict__ bias,
    float* __restrict__ C, int ldc,
    int M, int K,
    int mode, const int* __restrict__ tokens, int Tp, int Bp)
{
    __shared__ __half As[128][40];   // 32 used + 8 pad (80B row stride)
    __shared__ __half Bs[128][40];

    const int m0 = blockIdx.x * 128;
    const int n0 = blockIdx.y * 128;
    const int tid  = threadIdx.x;
    const int wid  = tid >> 5;
    const int lane = tid & 31;
    const int warp_m = wid >> 1;          // 0..3 -> 32 M rows
    const int warp_n = wid & 1;           // 0..1 -> 64 N cols
    const int grp  = lane >> 2;
    const int qid  = lane & 3;

    // global->smem: 2 units per thread, unit = 8 halves (16B)
    const int u0 = tid, u1 = tid + 256;   // units 0..511: row=u>>2, seg=u&3
    const __half* arow0 = nullptr;
    const __half* arow1 = nullptr;
    {
        int r0i = u0 >> 2, r1i = u1 >> 2;
        int am0 = m0 + r0i, am1 = m0 + r1i;
        long r;
        if (am0 < M) {
            if (mode == 0) r = am0;
            else if (mode == 1) r = tokens[am0];
            else r = (long)(am0 % Tp) * Bp + (am0 / Tp);
            arow0 = A + r * (long)lda;
        }
        if (am1 < M) {
            if (mode == 0) r = am1;
            else if (mode == 1) r = tokens[am1];
            else r = (long)(am1 % Tp) * Bp + (am1 / Tp);
            arow1 = A + r * (long)lda;
        }
    }
    const __half* brow0 = Bm + (size_t)(n0 + (u0 >> 2)) * (size_t)ldb;
    const __half* brow1 = Bm + (size_t)(n0 + (u1 >> 2)) * (size_t)ldb;

    // ldmatrix base addresses
    uint32_t aBase[2];
#pragma unroll
    for (int mt = 0; mt < 2; mt++)
        aBase[mt] = smem_u32(&As[warp_m * 32 + mt * 16 + (lane & 15)][(lane >> 4) * 8]);
    uint32_t bBase[4];
#pragma unroll
    for (int p = 0; p < 4; p++)
        bBase[p] = smem_u32(&Bs[warp_n * 64 + p * 16 + ((lane >> 4) & 1) * 8 + (lane & 7)]
                              [((lane >> 3) & 1) * 8]);

    float acc[2][8][4];
#pragma unroll
    for (int i = 0; i < 2; i++)
#pragma unroll
        for (int j = 0; j < 8; j++)
#pragma unroll
            for (int c = 0; c < 4; c++) acc[i][j][c] = 0.0f;

    const uint4 zero4 = make_uint4(0, 0, 0, 0);

    for (int kb = 0; kb < K; kb += 32) {
        __syncthreads();
        {
            int seg0 = (u0 & 3) * 8, seg1 = (u1 & 3) * 8;
            uint4 av0 = arow0 ? *(const uint4*)(arow0 + kb + seg0) : zero4;
            uint4 av1 = arow1 ? *(const uint4*)(arow1 + kb + seg1) : zero4;
            uint4 bv0 = *(const uint4*)(brow0 + kb + seg0);
            uint4 bv1 = *(const uint4*)(brow1 + kb + seg1);
            *(uint4*)&As[u0 >> 2][seg0] = av0;
            *(uint4*)&As[u1 >> 2][seg1] = av1;
            *(uint4*)&Bs[u0 >> 2][seg0] = bv0;
            *(uint4*)&Bs[u1 >> 2][seg1] = bv1;
        }
        __syncthreads();

#pragma unroll
        for (int ks = 0; ks < 32; ks += 16) {
            uint32_t af[2][4];
#pragma unroll
            for (int mt = 0; mt < 2; mt++) {
                asm volatile("ldmatrix.sync.aligned.m8n8.x4.shared.b16 {%0,%1,%2,%3}, [%4];"
                             : "=r"(af[mt][0]), "=r"(af[mt][1]), "=r"(af[mt][2]), "=r"(af[mt][3])
                             : "r"(aBase[mt] + ks * 2));
            }
            uint32_t bf[8][2];
#pragma unroll
            for (int p = 0; p < 4; p++) {
                asm volatile("ldmatrix.sync.aligned.m8n8.x4.shared.b16 {%0,%1,%2,%3}, [%4];"
                             : "=r"(bf[2 * p][0]), "=r"(bf[2 * p][1]),
                               "=r"(bf[2 * p + 1][0]), "=r"(bf[2 * p + 1][1])
                             : "r"(bBase[p] + ks * 2));
            }
#pragma unroll
            for (int mt = 0; mt < 2; mt++)
#pragma unroll
                for (int nt = 0; nt < 8; nt++) {
                    asm volatile(
                        "mma.sync.aligned.m16n8k16.row.col.f32.f16.f16.f32 "
                        "{%0,%1,%2,%3}, {%4,%5,%6,%7}, {%8,%9}, {%0,%1,%2,%3};\n"
                        : "+f"(acc[mt][nt][0]), "+f"(acc[mt][nt][1]),
                          "+f"(acc[mt][nt][2]), "+f"(acc[mt][nt][3])
                        : "r"(af[mt][0]), "r"(af[mt][1]), "r"(af[mt][2]), "r"(af[mt][3]),
                          "r"(bf[nt][0]), "r"(bf[nt][1]));
                }
        }
    }

    // epilogue
#pragma unroll
    for (int mt = 0; mt < 2; mt++) {
#pragma unroll
        for (int half = 0; half < 2; half++) {
            int m = m0 + warp_m * 32 + mt * 16 + grp + half * 8;
            if (m >= M) continue;
            float* crow = C + (size_t)m * (size_t)ldc;
#pragma unroll
            for (int nt = 0; nt < 8; nt++) {
                int col = n0 + warp_n * 64 + nt * 8 + 2 * qid;
                float v0 = acc[mt][nt][half * 2 + 0];
                float v1 = acc[mt][nt][half * 2 + 1];
                if (bias) { v0 += bias[col]; v1 += bias[col + 1]; }
                *(float2*)(crow + col) = make_float2(v0, v1);
            }
        }
    }
}

// ---------------- fused persistent GRU recurrence (unchanged) ----------------
__global__ void __launch_bounds__(256, 1) gru_persistent(
    const float* __restrict__ gx,
    const float* __restrict__ gx2,
    const float* __restrict__ Whh,
    const float* __restrict__ bhh,
    const float* __restrict__ h0, int h0stride,
    float* __restrict__ hA, float* __restrict__ hB,
    float* __restrict__ states,
    int T)
{
    __shared__ float hs[64][KT + 4];
    __shared__ float ws[24][KT + 4];

    const int tid = threadIdx.x;
    const int jj  = tid & 7;
    const int rg  = tid >> 3;
    const int b0  = rg * 2;
    const int b1  = b0 + 1;
    const int j0  = blockIdx.x * 8;
    const int j   = j0 + jj;

    const float bh0 = bhh[j];
    const float bh1 = bhh[H + j];
    const float bh2 = bhh[2 * H + j];

    unsigned sense = 0;
    if (tid == 0) sense = g_bar_sense;

    for (int t = 0; t < T; t++) {
        const float* hin; int hstride; float* hout;
        if (states) {
            hin = (t == 0) ? h0 : states + (size_t)(t - 1) * B_BATCH * H;
            hstride = (t == 0) ? h0stride : H;
            hout = states + (size_t)t * B_BATCH * H;
        } else {
            hin = (t == 0) ? h0 : (((t - 1) & 1) ? hB : hA);
            hstride = (t == 0) ? h0stride : H;
            hout = (t & 1) ? hB : hA;
        }

        float a00 = 0.f, a01 = 0.f, a10 = 0.f, a11 = 0.f, a20 = 0.f, a21 = 0.f;

        for (int kb = 0; kb < H; kb += KT) {
            __syncthreads();
#pragma unroll
            for (int i = 0; i < 8; i++) {
                int idx = tid + i * 256;
                int bb = idx >> 5, kq = idx & 31;
                float4 v = *(const float4*)(hin + (size_t)bb * hstride + kb + kq * 4);
                *(float4*)&hs[bb][kq * 4] = v;
            }
#pragma unroll
            for (int i = 0; i < 3; i++) {
                int idx = tid + i * 256;
                int c = idx >> 5, kq = idx & 31;
                int g = c >> 3, cj = c & 7;
                float4 v = *(const float4*)(Whh + (size_t)(g * H + j0 + cj) * H + kb + kq * 4);
                *(float4*)&ws[c][kq * 4] = v;
            }
            __syncthreads();
#pragma unroll 8
            for (int k = 0; k < KT; k += 4) {
                float4 hv0 = *(const float4*)&hs[b0][k];
                float4 hv1 = *(const float4*)&hs[b1][k];
                float4 w0  = *(const float4*)&ws[jj][k];
                float4 w1  = *(const float4*)&ws[8 + jj][k];
                float4 w2  = *(const float4*)&ws[16 + jj][k];
                a00 += w0.x * hv0.x; a00 += w0.y * hv0.y; a00 += w0.z * hv0.z; a00 += w0.w * hv0.w;
                a01 += w0.x * hv1.x; a01 += w0.y * hv1.y; a01 += w0.z * hv1.z; a01 += w0.w * hv1.w;
                a10 += w1.x * hv0.x; a10 += w1.y * hv0.y; a10 += w1.z * hv0.z; a10 += w1.w * hv0.w;
                a11 += w1.x * hv1.x; a11 += w1.y * hv1.y; a11 += w1.z * hv1.z; a11 += w1.w * hv1.w;
                a20 += w2.x * hv0.x; a20 += w2.y * hv0.y; a20 += w2.z * hv0.z; a20 += w2.w * hv0.w;
                a21 += w2.x * hv1.x; a21 += w2.y * hv1.y; a21 += w2.z * hv1.z; a21 += w2.w * hv1.w;
            }
        }

        const float* gxt = gx + (size_t)t * B_BATCH * H3;
        float hp0 = hin[(size_t)b0 * hstride + j];
        float hp1 = hin[(size_t)b1 * hstride + j];
        {
            float xr = gxt[(size_t)b0 * H3 + j];
            float xz = gxt[(size_t)b0 * H3 + H + j];
            float xn = gxt[(size_t)b0 * H3 + 2 * H + j];
            if (gx2) {
                xr += gx2[(size_t)b0 * H3 + j];
                xz += gx2[(size_t)b0 * H3 + H + j];
                xn += gx2[(size_t)b0 * H3 + 2 * H + j];
            }
            float r = 1.0f / (1.0f + __expf(-(xr + a00 + bh0)));
            float z = 1.0f / (1.0f + __expf(-(xz + a10 + bh1)));
            float n = tanhf(xn + r * (a20 + bh2));
            hout[(size_t)b0 * H + j] = (1.0f - z) * n + z * hp0;
        }
        {
            float xr = gxt[(size_t)b1 * H3 + j];
            float xz = gxt[(size_t)b1 * H3 + H + j];
            float xn = gxt[(size_t)b1 * H3 + 2 * H + j];
            if (gx2) {
                xr += gx2[(size_t)b1 * H3 + j];
                xz += gx2[(size_t)b1 * H3 + H + j];
                xn += gx2[(size_t)b1 * H3 + 2 * H + j];
            }
            float r = 1.0f / (1.0f + __expf(-(xr + a01 + bh0)));
            float z = 1.0f / (1.0f + __expf(-(xz + a11 + bh1)));
            float n = tanhf(xn + r * (a21 + bh2));
            hout[(size_t)b1 * H + j] = (1.0f - z) * n + z * hp1;
        }
        __threadfence();
        grid_barrier(sense);
    }
}

// ---------------- host driver ----------------
extern "C" void kernel_launch(void* const* d_in, const int* in_sizes, int n_in,
                              void* d_out, int out_size)
{
    (void)n_in; (void)out_size;
    const int* x      = (const int*)d_in[0];
    const int* labels = (const int*)d_in[1];
    const int* bosp   = nullptr;
    int idx = 2;
    if (in_sizes[2] == 1) { bosp = (const int*)d_in[2]; idx = 3; }
    const float* enc_emb  = (const float*)d_in[idx + 0];
    const float* enc_Wih  = (const float*)d_in[idx + 1];
    const float* enc_Whh  = (const float*)d_in[idx + 2];
    const float* enc_bih  = (const float*)d_in[idx + 3];
    const float* enc_bhh  = (const float*)d_in[idx + 4];
    const float* dec_emb  = (const float*)d_in[idx + 5];
    const float* dec_Wih  = (const float*)d_in[idx + 6];
    const float* dec_Whh  = (const float*)d_in[idx + 7];
    const float* dec_bih  = (const float*)d_in[idx + 8];
    const float* dec_bhh  = (const float*)d_in[idx + 9];
    const float* dec_init = (const float*)d_in[idx + 10];
    const float* lin_W    = (const float*)d_in[idx + 11];
    const float* lin_b    = (const float*)d_in[idx + 12];
    float* out = (float*)d_out;

    float *gxenc, *gxdec, *ctx, *hA, *hB, *h0buf, *states;
    __half *embE, *embD, *wihE, *wihD, *linW, *statesH, *hBH;
    int *etok, *dtok;
    cudaGetSymbolAddress((void**)&gxenc,   g_Gx_enc);
    cudaGetSymbolAddress((void**)&gxdec,   g_Gx_dec);
    cudaGetSymbolAddress((void**)&ctx,     g_ctx);
    cudaGetSymbolAddress((void**)&hA,      g_hA);
    cudaGetSymbolAddress((void**)&hB,      g_hB);
    cudaGetSymbolAddress((void**)&h0buf,   g_h0);
    cudaGetSymbolAddress((void**)&states,  g_states);
    cudaGetSymbolAddress((void**)&etok,    g_etok);
    cudaGetSymbolAddress((void**)&dtok,    g_dtok);
    cudaGetSymbolAddress((void**)&embE,    g_embE);
    cudaGetSymbolAddress((void**)&embD,    g_embD);
    cudaGetSymbolAddress((void**)&wihE,    g_wihE);
    cudaGetSymbolAddress((void**)&wihD,    g_wihD);
    cudaGetSymbolAddress((void**)&linW,    g_linW);
    cudaGetSymbolAddress((void**)&statesH, g_statesH);
    cudaGetSymbolAddress((void**)&hBH,     g_hBH);

    build_tokens<<<48, 256>>>(x, labels, bosp);
    zero_kernel<<<4, 256>>>(h0buf, H);

    // fp32 -> fp16 operand conversions
    conv_h<<<(VOCAB * D_EMB / 4 + 255) / 256, 256>>>(enc_emb, embE, VOCAB * D_EMB / 4);
    conv_h<<<(VOCAB * D_EMB / 4 + 255) / 256, 256>>>(dec_emb, embD, VOCAB * D_EMB / 4);
    conv_h<<<(H3 * D_EMB / 4 + 255) / 256, 256>>>(enc_Wih, wihE, H3 * D_EMB / 4);
    conv_h<<<(H3 * (D_EMB + H) / 4 + 255) / 256, 256>>>(dec_Wih, wihD, H3 * (D_EMB + H) / 4);
    conv_h<<<(VOCAB * H / 4 + 255) / 256, 256>>>(lin_W, linW, VOCAB * H / 4);

    // encoder input projections: (8192 x 3072 x 512)
    h16_gemm<<<dim3((T_ENC * B_BATCH) / 128, H3 / 128), 256>>>(
        embE, D_EMB, wihE, D_EMB, enc_bih,
        gxenc, H3, T_ENC * B_BATCH, D_EMB, 1, etok, 0, 0);

    // encoder recurrence -> final state in hB
    gru_persistent<<<NBLK, 256>>>(gxenc, nullptr, enc_Whh, enc_bhh,
                                  h0buf, 0, hA, hB, nullptr, T_ENC);

    // decoder word projections: (4096 x 3072 x 512)   [lda FIXED: D_EMB]
    h16_gemm<<<dim3((T_DEC * B_BATCH) / 128, H3 / 128), 256>>>(
        embD, D_EMB, wihD, D_EMB + H, dec_bih,
        gxdec, H3, T_DEC * B_BATCH, D_EMB, 1, dtok, 0, 0);

    // ctx projection: (64 x 3072 x 1024); A = hB in fp16
    conv_h<<<(B_BATCH * H / 4 + 255) / 256, 256>>>(hB, hBH, B_BATCH * H / 4);
    h16_gemm<<<dim3(1, H3 / 128), 256>>>(
        hBH, H, wihD + D_EMB, D_EMB + H, nullptr,
        ctx, H3, B_BATCH, H, 0, nullptr, 0, 0);

    // decoder recurrence -> states [t][b][H]
    gru_persistent<<<NBLK, 256>>>(gxdec, ctx, dec_Whh, dec_bhh,
                                  dec_init, 0, nullptr, nullptr, states, T_DEC);

    // states -> fp16 (layout preserved; GEMM mode 2 permutes rows)
    conv_h<<<(M_ROWS * H / 4 + 255) / 256, 256>>>(states, statesH, M_ROWS * H / 4);

    // output GEMM: (4096 x 32000 x 1024), logits[b*T+t][v]
    h16_gemm<<<dim3(M_ROWS / 128, VOCAB / 128), 256>>>(
        statesH, H, linW, H, lin_b,
        out, VOCAB, M_ROWS, H, 2, nullptr, T_DEC, B_BATCH);
}